// round 1
// baseline (speedup 1.0000x reference)
#include <cuda_runtime.h>
#include <math.h>

#define BB 8
#define NN 16384
#define MM 128
#define CC 81
#define KPOS 128
#define KNEG 128
#define NSAMP 256
#define BGCLS (CC - 1)

// ---------------- scratch (device globals; no allocation) ----------------
__device__ float g_hbb_tgt[BB][MM][4];   // GT AABBs
__device__ float g_boxt[BB][MM][5];      // GT cv2 (cx,cy,w,h,ang)
__device__ float g_miou[BB][NN];         // per-pred max IoU
__device__ int   g_match[BB][NN];        // per-pred argmax GT
__device__ unsigned long long g_kpos[BB][NN];  // sort keys for positive top-k
__device__ unsigned long long g_kneg[BB][NN];  // sort keys for negative top-k
__device__ float g_loss[BB][2];          // per-batch (cls, reg)

// monotone float->uint mapping (total order, matches float compare)
__device__ __forceinline__ unsigned ford(float f) {
    unsigned u = __float_as_uint(f);
    return (u & 0x80000000u) ? ~u : (u | 0x80000000u);
}

// ---------------- K1: GT prep ----------------
__global__ void k_gt(const float* __restrict__ rt) {
    int b = blockIdx.x, m = threadIdx.x;
    const float* v = rt + ((size_t)b * MM + m) * 8;
    float x0 = v[0], y0 = v[1], x1 = v[2], y1 = v[3];
    float x2 = v[4], y2 = v[5], x3 = v[6], y3 = v[7];
    g_hbb_tgt[b][m][0] = fminf(fminf(x0, x1), fminf(x2, x3));
    g_hbb_tgt[b][m][1] = fminf(fminf(y0, y1), fminf(y2, y3));
    g_hbb_tgt[b][m][2] = fmaxf(fmaxf(x0, x1), fmaxf(x2, x3));
    g_hbb_tgt[b][m][3] = fmaxf(fmaxf(y0, y1), fmaxf(y2, y3));
    float cx = (x0 + x1 + x2 + x3) * 0.25f;
    float cy = (y0 + y1 + y2 + y3) * 0.25f;
    float e1x = x1 - x0, e1y = y1 - y0;
    float e2x = x3 - x0, e2y = y3 - y0;
    g_boxt[b][m][0] = cx;
    g_boxt[b][m][1] = cy;
    g_boxt[b][m][2] = sqrtf(e1x * e1x + e1y * e1y);
    g_boxt[b][m][3] = sqrtf(e2x * e2x + e2y * e2y);
    g_boxt[b][m][4] = atan2f(e1y, e1x);
}

// ---------------- K2: per-pred hbb + IoU vs all GT + sort keys ----------------
__global__ void k_iou(const float* __restrict__ bp) {
    __shared__ float sh[MM * 4];
    int b = blockIdx.y;
    int tid = threadIdx.x;
    for (int i = tid; i < MM * 4; i += blockDim.x)
        sh[i] = ((const float*)g_hbb_tgt[b])[i];
    __syncthreads();

    int n = blockIdx.x * blockDim.x + tid;
    const float* p = bp + ((size_t)b * NN + n) * 5;
    float cx = p[0], cy = p[1], w = p[2], h = p[3], a = p[4];
    float c = cosf(a), s = sinf(a);
    float dx = w * 0.5f, dy = h * 0.5f;
    // rotated corners (same construction as reference)
    float xs0 = cx - dx * c + dy * s;
    float xs1 = cx + dx * c + dy * s;
    float xs2 = cx + dx * c - dy * s;
    float xs3 = cx - dx * c - dy * s;
    float ys0 = cy - dx * s - dy * c;
    float ys1 = cy + dx * s - dy * c;
    float ys2 = cy + dx * s + dy * c;
    float ys3 = cy - dx * s + dy * c;
    float pmnx = fminf(fminf(xs0, xs1), fminf(xs2, xs3));
    float pmxx = fmaxf(fmaxf(xs0, xs1), fmaxf(xs2, xs3));
    float pmny = fminf(fminf(ys0, ys1), fminf(ys2, ys3));
    float pmxy = fmaxf(fmaxf(ys0, ys1), fmaxf(ys2, ys3));
    float area_a = (pmxx - pmnx) * (pmxy - pmny);

    float best = -1.0f;
    int bestj = 0;
    #pragma unroll 4
    for (int j = 0; j < MM; j++) {
        float gx1 = sh[j * 4 + 0], gy1 = sh[j * 4 + 1];
        float gx2 = sh[j * 4 + 2], gy2 = sh[j * 4 + 3];
        float iw = fmaxf(fminf(pmxx, gx2) - fmaxf(pmnx, gx1), 0.0f);
        float ih = fmaxf(fminf(pmxy, gy2) - fmaxf(pmny, gy1), 0.0f);
        float inter = iw * ih;
        float area_b = (gx2 - gx1) * (gy2 - gy1);
        float un = area_a + area_b - inter;
        float iou = inter / fmaxf(un, 1e-7f);
        if (iou > best) { best = iou; bestj = j; }  // first-max on ties
    }
    g_miou[b][n] = best;
    g_match[b][n] = bestj;

    bool pos = (best >= 0.5f);
    // neg key: ascending max_iou, ties smaller index first; positives forced last
    unsigned long long kn = pos
        ? ((0xFFFFFFFFull << 32) | (unsigned)n)
        : (((unsigned long long)ford(best) << 32) | (unsigned)n);
    // pos key: descending pos_score (= max_iou if pos else -1), ties smaller index
    float score = pos ? best : -1.0f;
    unsigned long long kp = (((unsigned long long)(~ford(score))) << 32) | (unsigned)n;
    g_kneg[b][n] = kn;
    g_kpos[b][n] = kp;
}

// ---------------- K3: full bitonic sort of one key array in shared ----------------
extern __shared__ unsigned long long s_keys[];
__global__ __launch_bounds__(1024) void k_sort() {
    int b = blockIdx.x >> 1;
    unsigned long long* g = (blockIdx.x & 1) ? g_kneg[b] : g_kpos[b];
    int tid = threadIdx.x;
    for (int i = tid; i < NN; i += 1024) s_keys[i] = g[i];
    __syncthreads();
    for (unsigned k = 2; k <= NN; k <<= 1) {
        for (unsigned j = k >> 1; j > 0; j >>= 1) {
            for (unsigned i = tid; i < NN; i += 1024) {
                unsigned ixj = i ^ j;
                if (ixj > i) {
                    bool up = ((i & k) == 0);
                    unsigned long long A = s_keys[i], Bv = s_keys[ixj];
                    if ((A > Bv) == up) { s_keys[i] = Bv; s_keys[ixj] = A; }
                }
            }
            __syncthreads();
        }
    }
    for (int i = tid; i < NN; i += 1024) g[i] = s_keys[i];
}

// ---------------- K4: gather samples, softmax-NLL + smooth-L1, block reduce ----------------
__global__ void k_loss(const float* __restrict__ bp,
                       const float* __restrict__ cp,
                       const int* __restrict__ labels) {
    __shared__ float s_cls[NSAMP];
    __shared__ float s_reg[NSAMP];
    int b = blockIdx.x;
    int t = threadIdx.x;
    bool is_pos_slot = (t < KPOS);
    unsigned long long key = is_pos_slot ? g_kpos[b][t] : g_kneg[b][t - KPOS];
    int idx = (int)(key & 0xFFFFFFFFull);
    float miou = g_miou[b][idx];
    bool pos = (miou >= 0.5f);
    bool valid = is_pos_slot ? pos : (!pos);
    int m = g_match[b][idx];
    int tgt = pos ? labels[b * MM + m] : BGCLS;

    const float* lg = cp + ((size_t)b * NN + idx) * CC;
    float mx = -INFINITY;
    #pragma unroll
    for (int cc = 0; cc < CC; cc++) mx = fmaxf(mx, __ldg(lg + cc));
    float se = 0.0f;
    #pragma unroll
    for (int cc = 0; cc < CC; cc++) se += expf(__ldg(lg + cc) - mx);
    float nll = logf(se) + mx - __ldg(lg + tgt);
    s_cls[t] = valid ? nll : 0.0f;

    float reg = 0.0f;
    if (is_pos_slot && valid) {
        const float* pb = bp + ((size_t)b * NN + idx) * 5;
        const float* gb = g_boxt[b][m];
        #pragma unroll
        for (int d = 0; d < 5; d++) {
            float ad = fabsf(pb[d] - gb[d]);
            reg += (ad < 1.0f) ? 0.5f * ad * ad : ad - 0.5f;
        }
    }
    s_reg[t] = reg;
    __syncthreads();
    // deterministic tree reduction
    for (int st = NSAMP / 2; st > 0; st >>= 1) {
        if (t < st) {
            s_cls[t] += s_cls[t + st];
            s_reg[t] += s_reg[t + st];
        }
        __syncthreads();
    }
    if (t == 0) {
        g_loss[b][0] = s_cls[0];
        g_loss[b][1] = s_reg[0];
    }
}

// ---------------- K5: fixed-order final combine ----------------
__global__ void k_final(float* __restrict__ out) {
    float cs = 0.0f, rs = 0.0f;
    for (int b = 0; b < BB; b++) { cs += g_loss[b][0]; rs += g_loss[b][1]; }
    cs /= (float)BB;
    rs /= (float)BB;
    out[0] = cs + rs;
    out[1] = cs;
    out[2] = rs;
}

// ---------------- launch ----------------
extern "C" void kernel_launch(void* const* d_in, const int* in_sizes, int n_in,
                              void* d_out, int out_size) {
    const float* box_pred   = (const float*)d_in[0];  // [8,16384,5]
    const float* class_pred = (const float*)d_in[1];  // [8,16384,81]
    const float* regr_tgt   = (const float*)d_in[2];  // [8,128,4,2]
    const int*   cls_tgt    = (const int*)d_in[3];    // [8,128]
    (void)in_sizes; (void)n_in; (void)out_size;

    cudaFuncSetAttribute(k_sort, cudaFuncAttributeMaxDynamicSharedMemorySize,
                         NN * (int)sizeof(unsigned long long));

    k_gt<<<BB, MM>>>(regr_tgt);
    k_iou<<<dim3(NN / 256, BB), 256>>>(box_pred);
    k_sort<<<2 * BB, 1024, NN * sizeof(unsigned long long)>>>();
    k_loss<<<BB, NSAMP>>>(box_pred, class_pred, cls_tgt);
    k_final<<<1, 1>>>((float*)d_out);
}

// round 2
// speedup vs baseline: 2.5840x; 2.5840x over previous
#include <cuda_runtime.h>
#include <math.h>

#define BB 8
#define NN 16384
#define MM 128
#define CC 81
#define KPOS 128
#define KNEG 128
#define NSAMP 256
#define BGCLS (CC - 1)
#define SEL_T 1024

typedef unsigned long long u64;

// ---------------- scratch (device globals; no allocation) ----------------
__device__ float g_hbb_tgt[BB][MM][4];   // GT AABBs
__device__ float g_boxt[BB][MM][5];      // GT cv2 (cx,cy,w,h,ang)
__device__ float g_miou[BB][NN];         // per-pred max IoU
__device__ int   g_match[BB][NN];        // per-pred argmax GT
__device__ int   g_selidx[BB][NSAMP];    // [0..127]=pos selection, [128..255]=neg selection
__device__ float g_part[BB][8][2];       // per-(batch, sample-block) partial (cls, reg)

// monotone float->uint mapping (total order, matches float compare)
__device__ __forceinline__ unsigned ford(float f) {
    unsigned u = __float_as_uint(f);
    return (u & 0x80000000u) ? ~u : (u | 0x80000000u);
}

// pos key: ascending = descending pos_score, ties smaller index first
__device__ __forceinline__ u64 make_key_pos(float miou, int n) {
    float score = (miou >= 0.5f) ? miou : -1.0f;
    return (((u64)(~ford(score))) << 32) | (unsigned)n;
}
// neg key: ascending max_iou among negatives, ties smaller index; positives last
__device__ __forceinline__ u64 make_key_neg(float miou, int n) {
    if (miou >= 0.5f) return (0xFFFFFFFFull << 32) | (unsigned)n;
    return (((u64)ford(miou)) << 32) | (unsigned)n;
}

// ---------------- K1: GT prep ----------------
__global__ void k_gt(const float* __restrict__ rt) {
    int b = blockIdx.x, m = threadIdx.x;
    const float* v = rt + ((size_t)b * MM + m) * 8;
    float x0 = v[0], y0 = v[1], x1 = v[2], y1 = v[3];
    float x2 = v[4], y2 = v[5], x3 = v[6], y3 = v[7];
    g_hbb_tgt[b][m][0] = fminf(fminf(x0, x1), fminf(x2, x3));
    g_hbb_tgt[b][m][1] = fminf(fminf(y0, y1), fminf(y2, y3));
    g_hbb_tgt[b][m][2] = fmaxf(fmaxf(x0, x1), fmaxf(x2, x3));
    g_hbb_tgt[b][m][3] = fmaxf(fmaxf(y0, y1), fmaxf(y2, y3));
    float cx = (x0 + x1 + x2 + x3) * 0.25f;
    float cy = (y0 + y1 + y2 + y3) * 0.25f;
    float e1x = x1 - x0, e1y = y1 - y0;
    float e2x = x3 - x0, e2y = y3 - y0;
    g_boxt[b][m][0] = cx;
    g_boxt[b][m][1] = cy;
    g_boxt[b][m][2] = sqrtf(e1x * e1x + e1y * e1y);
    g_boxt[b][m][3] = sqrtf(e2x * e2x + e2y * e2y);
    g_boxt[b][m][4] = atan2f(e1y, e1x);
}

// ---------------- K2: per-pred hbb + IoU vs all GT (max + argmax) ----------------
__global__ void k_iou(const float* __restrict__ bp) {
    __shared__ float sh[MM * 4];
    int b = blockIdx.y;
    int tid = threadIdx.x;
    for (int i = tid; i < MM * 4; i += blockDim.x)
        sh[i] = ((const float*)g_hbb_tgt[b])[i];
    __syncthreads();

    int n = blockIdx.x * blockDim.x + tid;
    const float* p = bp + ((size_t)b * NN + n) * 5;
    float cx = p[0], cy = p[1], w = p[2], h = p[3], a = p[4];
    float c = cosf(a), s = sinf(a);
    float dx = w * 0.5f, dy = h * 0.5f;
    float xs0 = cx - dx * c + dy * s;
    float xs1 = cx + dx * c + dy * s;
    float xs2 = cx + dx * c - dy * s;
    float xs3 = cx - dx * c - dy * s;
    float ys0 = cy - dx * s - dy * c;
    float ys1 = cy + dx * s - dy * c;
    float ys2 = cy + dx * s + dy * c;
    float ys3 = cy - dx * s + dy * c;
    float pmnx = fminf(fminf(xs0, xs1), fminf(xs2, xs3));
    float pmxx = fmaxf(fmaxf(xs0, xs1), fmaxf(xs2, xs3));
    float pmny = fminf(fminf(ys0, ys1), fminf(ys2, ys3));
    float pmxy = fmaxf(fmaxf(ys0, ys1), fmaxf(ys2, ys3));
    float area_a = (pmxx - pmnx) * (pmxy - pmny);

    float best = -1.0f;
    int bestj = 0;
    #pragma unroll 4
    for (int j = 0; j < MM; j++) {
        float gx1 = sh[j * 4 + 0], gy1 = sh[j * 4 + 1];
        float gx2 = sh[j * 4 + 2], gy2 = sh[j * 4 + 3];
        float iw = fmaxf(fminf(pmxx, gx2) - fmaxf(pmnx, gx1), 0.0f);
        float ih = fmaxf(fminf(pmxy, gy2) - fmaxf(pmny, gy1), 0.0f);
        float inter = iw * ih;
        float area_b = (gx2 - gx1) * (gy2 - gy1);
        float un = area_a + area_b - inter;
        float iou = inter / fmaxf(un, 1e-7f);
        if (iou > best) { best = iou; bestj = j; }  // first-max on ties
    }
    g_miou[b][n] = best;
    g_match[b][n] = bestj;
}

// ---------------- K3: exact top-128 via 64-bit radix select ----------------
extern __shared__ u64 sk[];  // NN keys, 128KB dynamic
__global__ __launch_bounds__(SEL_T) void k_select() {
    __shared__ unsigned hist[256];
    __shared__ int cnts[SEL_T];
    __shared__ int sh_digit, sh_below;
    int b = blockIdx.x >> 1, kind = blockIdx.x & 1, tid = threadIdx.x;

    for (int i = tid; i < NN; i += SEL_T) {
        float mi = g_miou[b][i];
        sk[i] = kind ? make_key_neg(mi, i) : make_key_pos(mi, i);
    }
    __syncthreads();

    u64 prefix = 0, mask = 0;
    int k = 128;
    for (int shift = 56; shift >= 0; shift -= 8) {
        if (tid < 256) hist[tid] = 0;
        __syncthreads();
        for (int i = tid; i < NN; i += SEL_T) {
            u64 key = sk[i];
            if ((key & mask) == prefix)
                atomicAdd(&hist[(unsigned)(key >> shift) & 255u], 1u);
        }
        __syncthreads();
        if (tid == 0) {
            unsigned c = 0; int d = 0;
            for (; d < 256; d++) {
                unsigned h = hist[d];
                if (c + h >= (unsigned)k) break;
                c += h;
            }
            sh_digit = d; sh_below = (int)c;
        }
        __syncthreads();
        prefix |= ((u64)sh_digit) << shift;
        mask |= (255ull << shift);
        k -= sh_below;
        __syncthreads();
    }

    // kth key == prefix (unique keys) -> exactly 128 keys <= prefix
    u64 kth = prefix;
    int c = 0;
    for (int i = tid; i < NN; i += SEL_T)
        if (sk[i] <= kth) c++;
    cnts[tid] = c;
    __syncthreads();
    if (tid == 0) {
        int acc = 0;
        for (int t = 0; t < SEL_T; t++) { int v = cnts[t]; cnts[t] = acc; acc += v; }
    }
    __syncthreads();
    int off = cnts[tid];
    for (int i = tid; i < NN; i += SEL_T)
        if (sk[i] <= kth) g_selidx[b][kind * 128 + off++] = (int)(sk[i] & 0xFFFFFFFFull);
}

// ---------------- K4: warp-per-sample softmax-NLL + smooth-L1 ----------------
__global__ __launch_bounds__(1024) void k_loss(const float* __restrict__ bp,
                                               const float* __restrict__ cp,
                                               const int* __restrict__ labels) {
    __shared__ float s_c[32], s_r[32];
    int b = blockIdx.y;
    int w = threadIdx.x >> 5, lane = threadIdx.x & 31;
    int s = blockIdx.x * 32 + w;                 // 0..255
    int idx = g_selidx[b][s];
    float miou = g_miou[b][idx];
    bool pos = (miou >= 0.5f);
    bool is_pos_slot = (s < KPOS);
    bool valid = is_pos_slot ? pos : (!pos);
    int m = g_match[b][idx];
    int tgt = pos ? labels[b * MM + m] : BGCLS;

    const float* lg = cp + ((size_t)b * NN + idx) * CC;
    float v0 = lg[lane];
    float v1 = (lane + 32 < CC) ? lg[lane + 32] : -INFINITY;
    float v2 = (lane + 64 < CC) ? lg[lane + 64] : -INFINITY;
    float mx = fmaxf(v0, fmaxf(v1, v2));
    #pragma unroll
    for (int o = 16; o; o >>= 1) mx = fmaxf(mx, __shfl_xor_sync(~0u, mx, o));
    float se = expf(v0 - mx);
    if (lane + 32 < CC) se += expf(v1 - mx);
    if (lane + 64 < CC) se += expf(v2 - mx);
    #pragma unroll
    for (int o = 16; o; o >>= 1) se += __shfl_xor_sync(~0u, se, o);

    if (lane == 0) {
        float nll = logf(se) + mx - __ldg(lg + tgt);
        s_c[w] = valid ? nll : 0.0f;
        float reg = 0.0f;
        if (is_pos_slot && valid) {
            const float* pb = bp + ((size_t)b * NN + idx) * 5;
            const float* gb = g_boxt[b][m];
            #pragma unroll
            for (int d = 0; d < 5; d++) {
                float ad = fabsf(pb[d] - gb[d]);
                reg += (ad < 1.0f) ? 0.5f * ad * ad : ad - 0.5f;
            }
        }
        s_r[w] = reg;
    }
    __syncthreads();
    if (threadIdx.x < 32) {
        float cv = s_c[lane], rv = s_r[lane];
        #pragma unroll
        for (int o = 16; o; o >>= 1) {
            cv += __shfl_xor_sync(~0u, cv, o);
            rv += __shfl_xor_sync(~0u, rv, o);
        }
        if (lane == 0) {
            g_part[b][blockIdx.x][0] = cv;
            g_part[b][blockIdx.x][1] = rv;
        }
    }
}

// ---------------- K5: fixed-order final combine ----------------
__global__ void k_final(float* __restrict__ out) {
    float cs = 0.0f, rs = 0.0f;
    for (int b = 0; b < BB; b++)
        for (int j = 0; j < 8; j++) { cs += g_part[b][j][0]; rs += g_part[b][j][1]; }
    cs /= (float)BB;
    rs /= (float)BB;
    out[0] = cs + rs;
    out[1] = cs;
    out[2] = rs;
}

// ---------------- launch ----------------
extern "C" void kernel_launch(void* const* d_in, const int* in_sizes, int n_in,
                              void* d_out, int out_size) {
    const float* box_pred   = (const float*)d_in[0];  // [8,16384,5]
    const float* class_pred = (const float*)d_in[1];  // [8,16384,81]
    const float* regr_tgt   = (const float*)d_in[2];  // [8,128,4,2]
    const int*   cls_tgt    = (const int*)d_in[3];    // [8,128]
    (void)in_sizes; (void)n_in; (void)out_size;

    cudaFuncSetAttribute(k_select, cudaFuncAttributeMaxDynamicSharedMemorySize,
                         NN * (int)sizeof(u64));

    k_gt<<<BB, MM>>>(regr_tgt);
    k_iou<<<dim3(NN / 256, BB), 256>>>(box_pred);
    k_select<<<2 * BB, SEL_T, NN * sizeof(u64)>>>();
    k_loss<<<dim3(8, BB), 1024>>>(box_pred, class_pred, cls_tgt);
    k_final<<<1, 1>>>((float*)d_out);
}

// round 3
// speedup vs baseline: 3.7235x; 1.4410x over previous
#include <cuda_runtime.h>
#include <math.h>

#define BB 8
#define NN 16384
#define MM 128
#define CC 81
#define KPOS 128
#define NSAMP 256
#define BGCLS (CC - 1)
#define SEL_T 1024
#define LOSS_BX 32          // k_loss grid.x; 8 warps/block -> 256 samples
#define NPART (LOSS_BX)

typedef unsigned long long u64;

// ---------------- scratch (device globals; no allocation) ----------------
__device__ float g_miou[BB][NN];
__device__ int   g_match[BB][NN];
__device__ int   g_selidx[BB][NSAMP];       // [0..127]=pos, [128..255]=neg
__device__ float g_part[BB][NPART][2];      // per-(batch, block) partial (cls, reg)
__device__ unsigned g_ticket;

// monotone float->uint (total order matches float compare)
__device__ __forceinline__ unsigned ford(float f) {
    unsigned u = __float_as_uint(f);
    return (u & 0x80000000u) ? ~u : (u | 0x80000000u);
}
__device__ __forceinline__ u64 make_key_pos(float miou, int n) {
    float score = (miou >= 0.5f) ? miou : -1.0f;
    return (((u64)(~ford(score))) << 32) | (unsigned)n;
}
__device__ __forceinline__ u64 make_key_neg(float miou, int n) {
    if (miou >= 0.5f) return (0xFFFFFFFFull << 32) | (unsigned)n;
    return (((u64)ford(miou)) << 32) | (unsigned)n;
}

// ---------------- K1: IoU max/argmax (GT prep fused in-block) ----------------
__global__ __launch_bounds__(256) void k_iou(const float* __restrict__ bp,
                                             const float* __restrict__ rt) {
    __shared__ float4 s_g[MM];
    __shared__ float  s_area[MM];
    int b = blockIdx.y;
    int tid = threadIdx.x;
    if (blockIdx.x == 0 && b == 0 && tid == 0) g_ticket = 0;  // reset for k_loss
    if (tid < MM) {
        const float* v = rt + ((size_t)b * MM + tid) * 8;
        float x0 = v[0], y0 = v[1], x1 = v[2], y1 = v[3];
        float x2 = v[4], y2 = v[5], x3 = v[6], y3 = v[7];
        float mnx = fminf(fminf(x0, x1), fminf(x2, x3));
        float mny = fminf(fminf(y0, y1), fminf(y2, y3));
        float mxx = fmaxf(fmaxf(x0, x1), fmaxf(x2, x3));
        float mxy = fmaxf(fmaxf(y0, y1), fmaxf(y2, y3));
        s_g[tid] = make_float4(mnx, mny, mxx, mxy);
        s_area[tid] = (mxx - mnx) * (mxy - mny);
    }
    __syncthreads();

    int n = blockIdx.x * blockDim.x + tid;
    const float* p = bp + ((size_t)b * NN + n) * 5;
    float cx = p[0], cy = p[1], w = p[2], h = p[3], a = p[4];
    float c = cosf(a), s = sinf(a);
    float dx = w * 0.5f, dy = h * 0.5f;
    float xs0 = cx - dx * c + dy * s;
    float xs1 = cx + dx * c + dy * s;
    float xs2 = cx + dx * c - dy * s;
    float xs3 = cx - dx * c - dy * s;
    float ys0 = cy - dx * s - dy * c;
    float ys1 = cy + dx * s - dy * c;
    float ys2 = cy + dx * s + dy * c;
    float ys3 = cy - dx * s + dy * c;
    float pmnx = fminf(fminf(xs0, xs1), fminf(xs2, xs3));
    float pmxx = fmaxf(fmaxf(xs0, xs1), fmaxf(xs2, xs3));
    float pmny = fminf(fminf(ys0, ys1), fminf(ys2, ys3));
    float pmxy = fmaxf(fmaxf(ys0, ys1), fmaxf(ys2, ys3));
    float area_a = (pmxx - pmnx) * (pmxy - pmny);

    float best = -1.0f;
    int bestj = 0;
    #pragma unroll 8
    for (int j = 0; j < MM; j++) {
        float4 g = s_g[j];
        float iw = fmaxf(fminf(pmxx, g.z) - fmaxf(pmnx, g.x), 0.0f);
        float ih = fmaxf(fminf(pmxy, g.w) - fmaxf(pmny, g.y), 0.0f);
        float inter = iw * ih;
        float un = area_a + s_area[j] - inter;
        float iou = inter / fmaxf(un, 1e-7f);
        if (iou > best) { best = iou; bestj = j; }  // first-max on ties
    }
    g_miou[b][n] = best;
    g_match[b][n] = bestj;
}

// ---------------- K2: exact top-128 via radix select (parallel scans) ----------------
extern __shared__ u64 sk[];  // NN keys = 128KB dynamic
__global__ __launch_bounds__(SEL_T) void k_select() {
    __shared__ unsigned hist[256];
    __shared__ unsigned s_w8[8];
    __shared__ int s_w32[32];
    __shared__ int sh_digit, sh_below;
    int b = blockIdx.x >> 1, kind = blockIdx.x & 1;
    int tid = threadIdx.x, lane = tid & 31, warp = tid >> 5;

    for (int i = tid; i < NN; i += SEL_T) {
        float mi = g_miou[b][i];
        sk[i] = kind ? make_key_neg(mi, i) : make_key_pos(mi, i);
    }
    __syncthreads();

    u64 prefix = 0, mask = 0;
    int k = 128;
    // key bits 16..31 are always zero (index < 2^14): 6 passes suffice
    const int shifts[6] = {56, 48, 40, 32, 8, 0};
    #pragma unroll
    for (int pi = 0; pi < 6; pi++) {
        int shift = shifts[pi];
        if (tid < 256) hist[tid] = 0;
        __syncthreads();
        for (int i = tid; i < NN; i += SEL_T) {
            u64 key = sk[i];
            if ((key & mask) == prefix)
                atomicAdd(&hist[(unsigned)(key >> shift) & 255u], 1u);
        }
        __syncthreads();
        // parallel 256-bin inclusive scan + crossing detection
        if (tid < 256) {
            unsigned v = hist[tid];
            unsigned inc = v;
            #pragma unroll
            for (int o = 1; o < 32; o <<= 1) {
                unsigned nv = __shfl_up_sync(~0u, inc, o);
                if (lane >= o) inc += nv;
            }
            if (lane == 31) s_w8[warp] = inc;
            __syncwarp();
            // stash inc for after barrier via register; barrier below
            hist[tid] = v;  // keep count
            // save inclusive-within-warp to reuse
            s_w32[0] = s_w32[0];  // no-op
            // store inc temporarily in a second pass after chunk offsets known
            // (we recompute below using s_w8)
            // -- handled after syncthreads --
            // store inc in shared? use a trick: write to hist later. Keep in reg:
            // we cannot keep across __syncthreads for other threads; same thread keeps reg.
            __syncthreads();
            if (tid == 0) {
                unsigned run = 0;
                #pragma unroll
                for (int j = 0; j < 8; j++) { unsigned t = s_w8[j]; s_w8[j] = run; run += t; }
            }
            __syncthreads();
            unsigned cum = inc + s_w8[warp];
            if ((int)cum >= k && (int)(cum - v) < k) {
                sh_digit = tid;
                sh_below = (int)(cum - v);
            }
        } else {
            __syncthreads();
            __syncthreads();
        }
        __syncthreads();
        prefix |= ((u64)sh_digit) << shift;
        mask |= (255ull << shift);
        k -= sh_below;
        __syncthreads();
    }

    // exactly 128 keys <= prefix (keys unique)
    u64 kth = prefix;
    int c = 0;
    for (int i = tid; i < NN; i += SEL_T)
        if (sk[i] <= kth) c++;
    int inc = c;
    #pragma unroll
    for (int o = 1; o < 32; o <<= 1) {
        int nv = __shfl_up_sync(~0u, inc, o);
        if (lane >= o) inc += nv;
    }
    if (lane == 31) s_w32[warp] = inc;
    __syncthreads();
    if (tid == 0) {
        int run = 0;
        #pragma unroll
        for (int j = 0; j < 32; j++) { int t = s_w32[j]; s_w32[j] = run; run += t; }
    }
    __syncthreads();
    int off = s_w32[warp] + inc - c;
    for (int i = tid; i < NN; i += SEL_T)
        if (sk[i] <= kth) g_selidx[b][kind * 128 + off++] = (int)(sk[i] & 0xFFFFFFFFull);
}

// ---------------- K3: warp-per-sample loss + fused final combine ----------------
__global__ __launch_bounds__(256) void k_loss(const float* __restrict__ bp,
                                              const float* __restrict__ cp,
                                              const float* __restrict__ rt,
                                              const int* __restrict__ labels,
                                              float* __restrict__ out) {
    __shared__ float s_c[8], s_r[8];
    __shared__ float s_fc[256], s_fr[256];
    __shared__ bool s_last;
    int b = blockIdx.y;
    int w = threadIdx.x >> 5, lane = threadIdx.x & 31;
    int s = blockIdx.x * 8 + w;                  // 0..255
    int idx = g_selidx[b][s];
    float miou = g_miou[b][idx];
    bool pos = (miou >= 0.5f);
    bool is_pos_slot = (s < KPOS);
    bool valid = is_pos_slot ? pos : (!pos);
    int m = g_match[b][idx];
    int tgt = pos ? labels[b * MM + m] : BGCLS;

    const float* lg = cp + ((size_t)b * NN + idx) * CC;
    float v0 = lg[lane];
    float v1 = (lane + 32 < CC) ? lg[lane + 32] : -INFINITY;
    float v2 = (lane + 64 < CC) ? lg[lane + 64] : -INFINITY;
    float mx = fmaxf(v0, fmaxf(v1, v2));
    #pragma unroll
    for (int o = 16; o; o >>= 1) mx = fmaxf(mx, __shfl_xor_sync(~0u, mx, o));
    float se = expf(v0 - mx);
    if (lane + 32 < CC) se += expf(v1 - mx);
    if (lane + 64 < CC) se += expf(v2 - mx);
    #pragma unroll
    for (int o = 16; o; o >>= 1) se += __shfl_xor_sync(~0u, se, o);

    if (lane == 0) {
        float nll = logf(se) + mx - __ldg(lg + tgt);
        s_c[w] = valid ? nll : 0.0f;
        float reg = 0.0f;
        if (is_pos_slot && valid) {
            const float* v = rt + ((size_t)b * MM + m) * 8;
            float x0 = v[0], y0 = v[1], x1 = v[2], y1 = v[3];
            float x2 = v[4], y2 = v[5], x3 = v[6], y3 = v[7];
            float e1x = x1 - x0, e1y = y1 - y0;
            float e2x = x3 - x0, e2y = y3 - y0;
            float gb[5];
            gb[0] = (x0 + x1 + x2 + x3) * 0.25f;
            gb[1] = (y0 + y1 + y2 + y3) * 0.25f;
            gb[2] = sqrtf(e1x * e1x + e1y * e1y);
            gb[3] = sqrtf(e2x * e2x + e2y * e2y);
            gb[4] = atan2f(e1y, e1x);
            const float* pb = bp + ((size_t)b * NN + idx) * 5;
            #pragma unroll
            for (int d = 0; d < 5; d++) {
                float ad = fabsf(pb[d] - gb[d]);
                reg += (ad < 1.0f) ? 0.5f * ad * ad : ad - 0.5f;
            }
        }
        s_r[w] = reg;
    }
    __syncthreads();
    if (threadIdx.x == 0) {
        float cv = 0.0f, rv = 0.0f;
        #pragma unroll
        for (int j = 0; j < 8; j++) { cv += s_c[j]; rv += s_r[j]; }
        g_part[b][blockIdx.x][0] = cv;
        g_part[b][blockIdx.x][1] = rv;
        __threadfence();
        unsigned done = atomicAdd(&g_ticket, 1u);
        s_last = (done == (unsigned)(BB * NPART - 1));
    }
    __syncthreads();
    if (s_last) {
        // final combine: 256 partial pairs, deterministic tree reduction
        const float* gp = &g_part[0][0][0];
        int t = threadIdx.x;
        s_fc[t] = gp[2 * t];
        s_fr[t] = gp[2 * t + 1];
        __syncthreads();
        for (int st = 128; st > 0; st >>= 1) {
            if (t < st) { s_fc[t] += s_fc[t + st]; s_fr[t] += s_fr[t + st]; }
            __syncthreads();
        }
        if (t == 0) {
            float cs = s_fc[0] / (float)BB;
            float rs = s_fr[0] / (float)BB;
            out[0] = cs + rs;
            out[1] = cs;
            out[2] = rs;
        }
    }
}

// ---------------- launch ----------------
extern "C" void kernel_launch(void* const* d_in, const int* in_sizes, int n_in,
                              void* d_out, int out_size) {
    const float* box_pred   = (const float*)d_in[0];  // [8,16384,5]
    const float* class_pred = (const float*)d_in[1];  // [8,16384,81]
    const float* regr_tgt   = (const float*)d_in[2];  // [8,128,4,2]
    const int*   cls_tgt    = (const int*)d_in[3];    // [8,128]
    (void)in_sizes; (void)n_in; (void)out_size;

    cudaFuncSetAttribute(k_select, cudaFuncAttributeMaxDynamicSharedMemorySize,
                         NN * (int)sizeof(u64));

    k_iou<<<dim3(NN / 256, BB), 256>>>(box_pred, regr_tgt);
    k_select<<<2 * BB, SEL_T, NN * sizeof(u64)>>>();
    k_loss<<<dim3(LOSS_BX, BB), 256>>>(box_pred, class_pred, regr_tgt, cls_tgt,
                                       (float*)d_out);
}

// round 4
// speedup vs baseline: 6.3325x; 1.7007x over previous
#include <cuda_runtime.h>
#include <math.h>

#define BB 8
#define NN 16384
#define MM 128
#define CC 81
#define KPOS 128
#define NSAMP 256
#define BGCLS (CC - 1)
#define SEL_T 1024
#define LOSS_BX 32
#define NPART (LOSS_BX)

typedef unsigned long long u64;

// ---------------- scratch ----------------
__device__ float g_miou[BB][NN];
__device__ int   g_match[BB][NN];
__device__ int   g_selidx[BB][NSAMP];
__device__ float g_part[BB][NPART][2];
__device__ unsigned g_ticket;

__device__ __forceinline__ unsigned ford(float f) {
    unsigned u = __float_as_uint(f);
    return (u & 0x80000000u) ? ~u : (u | 0x80000000u);
}
__device__ __forceinline__ u64 make_key_pos(float miou, int n) {
    float score = (miou >= 0.5f) ? miou : -1.0f;
    return (((u64)(~ford(score))) << 32) | (unsigned)n;
}
__device__ __forceinline__ u64 make_key_neg(float miou, int n) {
    if (miou >= 0.5f) return (0xFFFFFFFFull << 32) | (unsigned)n;
    return (((u64)ford(miou)) << 32) | (unsigned)n;
}

// ---------------- K1: IoU max/argmax, division-free inner loop ----------------
__global__ __launch_bounds__(256) void k_iou(const float* __restrict__ bp,
                                             const float* __restrict__ rt) {
    __shared__ float4 s_g[MM];
    __shared__ float  s_area[MM];
    int b = blockIdx.y;
    int tid = threadIdx.x;
    if (blockIdx.x == 0 && b == 0 && tid == 0) g_ticket = 0;
    if (tid < MM) {
        const float* v = rt + ((size_t)b * MM + tid) * 8;
        float x0 = v[0], y0 = v[1], x1 = v[2], y1 = v[3];
        float x2 = v[4], y2 = v[5], x3 = v[6], y3 = v[7];
        float mnx = fminf(fminf(x0, x1), fminf(x2, x3));
        float mny = fminf(fminf(y0, y1), fminf(y2, y3));
        float mxx = fmaxf(fmaxf(x0, x1), fmaxf(x2, x3));
        float mxy = fmaxf(fmaxf(y0, y1), fmaxf(y2, y3));
        s_g[tid] = make_float4(mnx, mny, mxx, mxy);
        s_area[tid] = (mxx - mnx) * (mxy - mny);
    }
    __syncthreads();

    int n = blockIdx.x * blockDim.x + tid;
    const float* p = bp + ((size_t)b * NN + n) * 5;
    float cx = p[0], cy = p[1], w = p[2], h = p[3], a = p[4];
    float c = cosf(a), s = sinf(a);
    float dx = w * 0.5f, dy = h * 0.5f;
    float xs0 = cx - dx * c + dy * s;
    float xs1 = cx + dx * c + dy * s;
    float xs2 = cx + dx * c - dy * s;
    float xs3 = cx - dx * c - dy * s;
    float ys0 = cy - dx * s - dy * c;
    float ys1 = cy + dx * s - dy * c;
    float ys2 = cy + dx * s + dy * c;
    float ys3 = cy - dx * s + dy * c;
    float pmnx = fminf(fminf(xs0, xs1), fminf(xs2, xs3));
    float pmxx = fmaxf(fmaxf(xs0, xs1), fmaxf(xs2, xs3));
    float pmny = fminf(fminf(ys0, ys1), fminf(ys2, ys3));
    float pmxy = fmaxf(fmaxf(ys0, ys1), fmaxf(ys2, ys3));
    float area_a = (pmxx - pmnx) * (pmxy - pmny);

    // 4 independent argmax chains (j-blocks of 32) tracking (inter, un) fractions.
    // iou_j > iou_best  <=>  inter_j * un_best > inter_best * un_j  (un > 0 always)
    float bi[4], bu[4];
    int bj[4];
    #pragma unroll
    for (int cch = 0; cch < 4; cch++) { bi[cch] = -1.0f; bu[cch] = 1.0f; bj[cch] = cch * 32; }

    #pragma unroll
    for (int cch = 0; cch < 4; cch++) {
        int base = cch * 32;
        #pragma unroll 8
        for (int jj = 0; jj < 32; jj++) {
            int j = base + jj;
            float4 g = s_g[j];
            float iw = fmaxf(fminf(pmxx, g.z) - fmaxf(pmnx, g.x), 0.0f);
            float ih = fmaxf(fminf(pmxy, g.w) - fmaxf(pmny, g.y), 0.0f);
            float inter = iw * ih;
            float un = area_a + s_area[j] - inter;
            if (inter * bu[cch] > bi[cch] * un) { bi[cch] = inter; bu[cch] = un; bj[cch] = j; }
        }
    }
    // merge chains; ties prefer lower-index chain (strict > keeps left operand)
    #pragma unroll
    for (int st = 1; st < 4; st <<= 1) {
        #pragma unroll
        for (int cch = 0; cch < 4; cch += 2 * st) {
            int o = cch + st;
            if (bi[o] * bu[cch] > bi[cch] * bu[o]) { bi[cch] = bi[o]; bu[cch] = bu[o]; bj[cch] = bj[o]; }
        }
    }
    float best = bi[0] / fmaxf(bu[0], 1e-7f);   // same rounding as reference for this j
    g_miou[b][n] = best;
    g_match[b][n] = bj[0];
}

// ---------------- K2: exact top-128 via radix select ----------------
extern __shared__ u64 sk[];
__global__ __launch_bounds__(SEL_T) void k_select() {
    __shared__ unsigned hist[256];
    __shared__ unsigned s_w8[8];
    __shared__ int s_w32[32];
    __shared__ int sh_digit, sh_below;
    int b = blockIdx.x >> 1, kind = blockIdx.x & 1;
    int tid = threadIdx.x, lane = tid & 31, warp = tid >> 5;

    for (int i = tid; i < NN; i += SEL_T) {
        float mi = g_miou[b][i];
        sk[i] = kind ? make_key_neg(mi, i) : make_key_pos(mi, i);
    }
    __syncthreads();

    u64 prefix = 0, mask = 0;
    int k = 128;
    const int shifts[6] = {56, 48, 40, 32, 8, 0};
    #pragma unroll
    for (int pi = 0; pi < 6; pi++) {
        int shift = shifts[pi];
        if (tid < 256) hist[tid] = 0;
        __syncthreads();
        for (int i = tid; i < NN; i += SEL_T) {
            u64 key = sk[i];
            if ((key & mask) == prefix)
                atomicAdd(&hist[(unsigned)(key >> shift) & 255u], 1u);
        }
        __syncthreads();
        if (tid < 256) {
            unsigned v = hist[tid];
            unsigned inc = v;
            #pragma unroll
            for (int o = 1; o < 32; o <<= 1) {
                unsigned nv = __shfl_up_sync(~0u, inc, o);
                if (lane >= o) inc += nv;
            }
            if (lane == 31) s_w8[warp] = inc;
            __syncthreads();
            if (tid == 0) {
                unsigned run = 0;
                #pragma unroll
                for (int j = 0; j < 8; j++) { unsigned t = s_w8[j]; s_w8[j] = run; run += t; }
            }
            __syncthreads();
            unsigned cum = inc + s_w8[warp];
            if ((int)cum >= k && (int)(cum - v) < k) {
                sh_digit = tid;
                sh_below = (int)(cum - v);
            }
        } else {
            __syncthreads();
            __syncthreads();
        }
        __syncthreads();
        prefix |= ((u64)sh_digit) << shift;
        mask |= (255ull << shift);
        k -= sh_below;
        __syncthreads();
    }

    u64 kth = prefix;
    int c = 0;
    for (int i = tid; i < NN; i += SEL_T)
        if (sk[i] <= kth) c++;
    int inc = c;
    #pragma unroll
    for (int o = 1; o < 32; o <<= 1) {
        int nv = __shfl_up_sync(~0u, inc, o);
        if (lane >= o) inc += nv;
    }
    if (lane == 31) s_w32[warp] = inc;
    __syncthreads();
    if (tid == 0) {
        int run = 0;
        #pragma unroll
        for (int j = 0; j < 32; j++) { int t = s_w32[j]; s_w32[j] = run; run += t; }
    }
    __syncthreads();
    int off = s_w32[warp] + inc - c;
    for (int i = tid; i < NN; i += SEL_T)
        if (sk[i] <= kth) g_selidx[b][kind * 128 + off++] = (int)(sk[i] & 0xFFFFFFFFull);
}

// ---------------- K3: warp-per-sample loss + fused final combine ----------------
__global__ __launch_bounds__(256) void k_loss(const float* __restrict__ bp,
                                              const float* __restrict__ cp,
                                              const float* __restrict__ rt,
                                              const int* __restrict__ labels,
                                              float* __restrict__ out) {
    __shared__ float s_c[8], s_r[8];
    __shared__ float s_fc[256], s_fr[256];
    __shared__ bool s_last;
    int b = blockIdx.y;
    int w = threadIdx.x >> 5, lane = threadIdx.x & 31;
    int s = blockIdx.x * 8 + w;
    int idx = g_selidx[b][s];
    float miou = g_miou[b][idx];
    bool pos = (miou >= 0.5f);
    bool is_pos_slot = (s < KPOS);
    bool valid = is_pos_slot ? pos : (!pos);
    int m = g_match[b][idx];
    int tgt = pos ? labels[b * MM + m] : BGCLS;

    const float* lg = cp + ((size_t)b * NN + idx) * CC;
    float v0 = lg[lane];
    float v1 = (lane + 32 < CC) ? lg[lane + 32] : -INFINITY;
    float v2 = (lane + 64 < CC) ? lg[lane + 64] : -INFINITY;
    float mx = fmaxf(v0, fmaxf(v1, v2));
    #pragma unroll
    for (int o = 16; o; o >>= 1) mx = fmaxf(mx, __shfl_xor_sync(~0u, mx, o));
    float se = expf(v0 - mx);
    if (lane + 32 < CC) se += expf(v1 - mx);
    if (lane + 64 < CC) se += expf(v2 - mx);
    #pragma unroll
    for (int o = 16; o; o >>= 1) se += __shfl_xor_sync(~0u, se, o);

    if (lane == 0) {
        float nll = logf(se) + mx - __ldg(lg + tgt);
        s_c[w] = valid ? nll : 0.0f;
        float reg = 0.0f;
        if (is_pos_slot && valid) {
            const float* v = rt + ((size_t)b * MM + m) * 8;
            float x0 = v[0], y0 = v[1], x1 = v[2], y1 = v[3];
            float x2 = v[4], y2 = v[5], x3 = v[6], y3 = v[7];
            float e1x = x1 - x0, e1y = y1 - y0;
            float e2x = x3 - x0, e2y = y3 - y0;
            float gb[5];
            gb[0] = (x0 + x1 + x2 + x3) * 0.25f;
            gb[1] = (y0 + y1 + y2 + y3) * 0.25f;
            gb[2] = sqrtf(e1x * e1x + e1y * e1y);
            gb[3] = sqrtf(e2x * e2x + e2y * e2y);
            gb[4] = atan2f(e1y, e1x);
            const float* pb = bp + ((size_t)b * NN + idx) * 5;
            #pragma unroll
            for (int d = 0; d < 5; d++) {
                float ad = fabsf(pb[d] - gb[d]);
                reg += (ad < 1.0f) ? 0.5f * ad * ad : ad - 0.5f;
            }
        }
        s_r[w] = reg;
    }
    __syncthreads();
    if (threadIdx.x == 0) {
        float cv = 0.0f, rv = 0.0f;
        #pragma unroll
        for (int j = 0; j < 8; j++) { cv += s_c[j]; rv += s_r[j]; }
        g_part[b][blockIdx.x][0] = cv;
        g_part[b][blockIdx.x][1] = rv;
        __threadfence();
        unsigned done = atomicAdd(&g_ticket, 1u);
        s_last = (done == (unsigned)(BB * NPART - 1));
    }
    __syncthreads();
    if (s_last) {
        const float* gp = &g_part[0][0][0];
        int t = threadIdx.x;
        s_fc[t] = gp[2 * t];
        s_fr[t] = gp[2 * t + 1];
        __syncthreads();
        for (int st = 128; st > 0; st >>= 1) {
            if (t < st) { s_fc[t] += s_fc[t + st]; s_fr[t] += s_fr[t + st]; }
            __syncthreads();
        }
        if (t == 0) {
            float cs = s_fc[0] / (float)BB;
            float rs = s_fr[0] / (float)BB;
            out[0] = cs + rs;
            out[1] = cs;
            out[2] = rs;
        }
    }
}

// ---------------- launch ----------------
extern "C" void kernel_launch(void* const* d_in, const int* in_sizes, int n_in,
                              void* d_out, int out_size) {
    const float* box_pred   = (const float*)d_in[0];
    const float* class_pred = (const float*)d_in[1];
    const float* regr_tgt   = (const float*)d_in[2];
    const int*   cls_tgt    = (const int*)d_in[3];
    (void)in_sizes; (void)n_in; (void)out_size;

    cudaFuncSetAttribute(k_select, cudaFuncAttributeMaxDynamicSharedMemorySize,
                         NN * (int)sizeof(u64));

    k_iou<<<dim3(NN / 256, BB), 256>>>(box_pred, regr_tgt);
    k_select<<<2 * BB, SEL_T, NN * sizeof(u64)>>>();
    k_loss<<<dim3(LOSS_BX, BB), 256>>>(box_pred, class_pred, regr_tgt, cls_tgt,
                                       (float*)d_out);
}

// round 5
// speedup vs baseline: 6.3813x; 1.0077x over previous
#include <cuda_runtime.h>
#include <math.h>

#define BB 8
#define NN 16384
#define MM 128
#define CC 81
#define KPOS 128
#define NSAMP 256
#define BGCLS (CC - 1)
#define SEL_T 1024
#define LOSS_BX 32
#define NPART (LOSS_BX)

typedef unsigned long long u64;

// ---------------- scratch ----------------
__device__ float g_miou[BB][NN];
__device__ int   g_match[BB][NN];
__device__ int   g_selidx[BB][NSAMP];
__device__ float g_part[BB][NPART][2];
__device__ unsigned g_ticket;

__device__ __forceinline__ unsigned ford(float f) {
    unsigned u = __float_as_uint(f);
    return (u & 0x80000000u) ? ~u : (u | 0x80000000u);
}
__device__ __forceinline__ u64 make_key_pos(float miou, int n) {
    float score = (miou >= 0.5f) ? miou : -1.0f;
    return (((u64)(~ford(score))) << 32) | (unsigned)n;
}
__device__ __forceinline__ u64 make_key_neg(float miou, int n) {
    if (miou >= 0.5f) return (0xFFFFFFFFull << 32) | (unsigned)n;
    return (((u64)ford(miou)) << 32) | (unsigned)n;
}

// ---------------- K1: IoU max/argmax, division-free inner loop ----------------
__global__ __launch_bounds__(256) void k_iou(const float* __restrict__ bp,
                                             const float* __restrict__ rt) {
    __shared__ float4 s_g[MM];
    __shared__ float  s_area[MM];
    int b = blockIdx.y;
    int tid = threadIdx.x;
    if (blockIdx.x == 0 && b == 0 && tid == 0) g_ticket = 0;
    if (tid < MM) {
        const float* v = rt + ((size_t)b * MM + tid) * 8;
        float x0 = v[0], y0 = v[1], x1 = v[2], y1 = v[3];
        float x2 = v[4], y2 = v[5], x3 = v[6], y3 = v[7];
        float mnx = fminf(fminf(x0, x1), fminf(x2, x3));
        float mny = fminf(fminf(y0, y1), fminf(y2, y3));
        float mxx = fmaxf(fmaxf(x0, x1), fmaxf(x2, x3));
        float mxy = fmaxf(fmaxf(y0, y1), fmaxf(y2, y3));
        s_g[tid] = make_float4(mnx, mny, mxx, mxy);
        s_area[tid] = (mxx - mnx) * (mxy - mny);
    }
    __syncthreads();

    int n = blockIdx.x * blockDim.x + tid;
    const float* p = bp + ((size_t)b * NN + n) * 5;
    float cx = p[0], cy = p[1], w = p[2], h = p[3], a = p[4];
    float c = cosf(a), s = sinf(a);
    float dx = w * 0.5f, dy = h * 0.5f;
    float xs0 = cx - dx * c + dy * s;
    float xs1 = cx + dx * c + dy * s;
    float xs2 = cx + dx * c - dy * s;
    float xs3 = cx - dx * c - dy * s;
    float ys0 = cy - dx * s - dy * c;
    float ys1 = cy + dx * s - dy * c;
    float ys2 = cy + dx * s + dy * c;
    float ys3 = cy - dx * s + dy * c;
    float pmnx = fminf(fminf(xs0, xs1), fminf(xs2, xs3));
    float pmxx = fmaxf(fmaxf(xs0, xs1), fmaxf(xs2, xs3));
    float pmny = fminf(fminf(ys0, ys1), fminf(ys2, ys3));
    float pmxy = fmaxf(fmaxf(ys0, ys1), fmaxf(ys2, ys3));
    float area_a = (pmxx - pmnx) * (pmxy - pmny);

    // 4 independent argmax chains (j-blocks of 32) tracking (inter, un) fractions.
    // iou_j > iou_best  <=>  inter_j * un_best > inter_best * un_j  (un > 0 always)
    float bi[4], bu[4];
    int bj[4];
    #pragma unroll
    for (int cch = 0; cch < 4; cch++) { bi[cch] = -1.0f; bu[cch] = 1.0f; bj[cch] = cch * 32; }

    #pragma unroll
    for (int cch = 0; cch < 4; cch++) {
        int base = cch * 32;
        #pragma unroll 8
        for (int jj = 0; jj < 32; jj++) {
            int j = base + jj;
            float4 g = s_g[j];
            float iw = fmaxf(fminf(pmxx, g.z) - fmaxf(pmnx, g.x), 0.0f);
            float ih = fmaxf(fminf(pmxy, g.w) - fmaxf(pmny, g.y), 0.0f);
            float inter = iw * ih;
            float un = area_a + s_area[j] - inter;
            if (inter * bu[cch] > bi[cch] * un) { bi[cch] = inter; bu[cch] = un; bj[cch] = j; }
        }
    }
    // merge chains; ties prefer lower-index chain (strict > keeps left operand)
    #pragma unroll
    for (int st = 1; st < 4; st <<= 1) {
        #pragma unroll
        for (int cch = 0; cch < 4; cch += 2 * st) {
            int o = cch + st;
            if (bi[o] * bu[cch] > bi[cch] * bu[o]) { bi[cch] = bi[o]; bu[cch] = bu[o]; bj[cch] = bj[o]; }
        }
    }
    float best = bi[0] / fmaxf(bu[0], 1e-7f);   // same rounding as reference for this j
    g_miou[b][n] = best;
    g_match[b][n] = bj[0];
}

// ---------------- K2: exact top-128 via radix select ----------------
extern __shared__ u64 sk[];
__global__ __launch_bounds__(SEL_T) void k_select() {
    __shared__ unsigned hist[256];
    __shared__ unsigned s_w8[8];
    __shared__ int s_w32[32];
    __shared__ int sh_digit, sh_below;
    int b = blockIdx.x >> 1, kind = blockIdx.x & 1;
    int tid = threadIdx.x, lane = tid & 31, warp = tid >> 5;

    for (int i = tid; i < NN; i += SEL_T) {
        float mi = g_miou[b][i];
        sk[i] = kind ? make_key_neg(mi, i) : make_key_pos(mi, i);
    }
    __syncthreads();

    u64 prefix = 0, mask = 0;
    int k = 128;
    const int shifts[6] = {56, 48, 40, 32, 8, 0};
    #pragma unroll
    for (int pi = 0; pi < 6; pi++) {
        int shift = shifts[pi];
        if (tid < 256) hist[tid] = 0;
        __syncthreads();
        for (int i = tid; i < NN; i += SEL_T) {
            u64 key = sk[i];
            if ((key & mask) == prefix)
                atomicAdd(&hist[(unsigned)(key >> shift) & 255u], 1u);
        }
        __syncthreads();
        if (tid < 256) {
            unsigned v = hist[tid];
            unsigned inc = v;
            #pragma unroll
            for (int o = 1; o < 32; o <<= 1) {
                unsigned nv = __shfl_up_sync(~0u, inc, o);
                if (lane >= o) inc += nv;
            }
            if (lane == 31) s_w8[warp] = inc;
            __syncthreads();
            if (tid == 0) {
                unsigned run = 0;
                #pragma unroll
                for (int j = 0; j < 8; j++) { unsigned t = s_w8[j]; s_w8[j] = run; run += t; }
            }
            __syncthreads();
            unsigned cum = inc + s_w8[warp];
            if ((int)cum >= k && (int)(cum - v) < k) {
                sh_digit = tid;
                sh_below = (int)(cum - v);
            }
        } else {
            __syncthreads();
            __syncthreads();
        }
        __syncthreads();
        prefix |= ((u64)sh_digit) << shift;
        mask |= (255ull << shift);
        k -= sh_below;
        __syncthreads();
    }

    u64 kth = prefix;
    int c = 0;
    for (int i = tid; i < NN; i += SEL_T)
        if (sk[i] <= kth) c++;
    int inc = c;
    #pragma unroll
    for (int o = 1; o < 32; o <<= 1) {
        int nv = __shfl_up_sync(~0u, inc, o);
        if (lane >= o) inc += nv;
    }
    if (lane == 31) s_w32[warp] = inc;
    __syncthreads();
    if (tid == 0) {
        int run = 0;
        #pragma unroll
        for (int j = 0; j < 32; j++) { int t = s_w32[j]; s_w32[j] = run; run += t; }
    }
    __syncthreads();
    int off = s_w32[warp] + inc - c;
    for (int i = tid; i < NN; i += SEL_T)
        if (sk[i] <= kth) g_selidx[b][kind * 128 + off++] = (int)(sk[i] & 0xFFFFFFFFull);
}

// ---------------- K3: warp-per-sample loss + fused final combine ----------------
__global__ __launch_bounds__(256) void k_loss(const float* __restrict__ bp,
                                              const float* __restrict__ cp,
                                              const float* __restrict__ rt,
                                              const int* __restrict__ labels,
                                              float* __restrict__ out) {
    __shared__ float s_c[8], s_r[8];
    __shared__ float s_fc[256], s_fr[256];
    __shared__ bool s_last;
    int b = blockIdx.y;
    int w = threadIdx.x >> 5, lane = threadIdx.x & 31;
    int s = blockIdx.x * 8 + w;
    int idx = g_selidx[b][s];
    float miou = g_miou[b][idx];
    bool pos = (miou >= 0.5f);
    bool is_pos_slot = (s < KPOS);
    bool valid = is_pos_slot ? pos : (!pos);
    int m = g_match[b][idx];
    int tgt = pos ? labels[b * MM + m] : BGCLS;

    const float* lg = cp + ((size_t)b * NN + idx) * CC;
    float v0 = lg[lane];
    float v1 = (lane + 32 < CC) ? lg[lane + 32] : -INFINITY;
    float v2 = (lane + 64 < CC) ? lg[lane + 64] : -INFINITY;
    float mx = fmaxf(v0, fmaxf(v1, v2));
    #pragma unroll
    for (int o = 16; o; o >>= 1) mx = fmaxf(mx, __shfl_xor_sync(~0u, mx, o));
    float se = expf(v0 - mx);
    if (lane + 32 < CC) se += expf(v1 - mx);
    if (lane + 64 < CC) se += expf(v2 - mx);
    #pragma unroll
    for (int o = 16; o; o >>= 1) se += __shfl_xor_sync(~0u, se, o);

    if (lane == 0) {
        float nll = logf(se) + mx - __ldg(lg + tgt);
        s_c[w] = valid ? nll : 0.0f;
        float reg = 0.0f;
        if (is_pos_slot && valid) {
            const float* v = rt + ((size_t)b * MM + m) * 8;
            float x0 = v[0], y0 = v[1], x1 = v[2], y1 = v[3];
            float x2 = v[4], y2 = v[5], x3 = v[6], y3 = v[7];
            float e1x = x1 - x0, e1y = y1 - y0;
            float e2x = x3 - x0, e2y = y3 - y0;
            float gb[5];
            gb[0] = (x0 + x1 + x2 + x3) * 0.25f;
            gb[1] = (y0 + y1 + y2 + y3) * 0.25f;
            gb[2] = sqrtf(e1x * e1x + e1y * e1y);
            gb[3] = sqrtf(e2x * e2x + e2y * e2y);
            gb[4] = atan2f(e1y, e1x);
            const float* pb = bp + ((size_t)b * NN + idx) * 5;
            #pragma unroll
            for (int d = 0; d < 5; d++) {
                float ad = fabsf(pb[d] - gb[d]);
                reg += (ad < 1.0f) ? 0.5f * ad * ad : ad - 0.5f;
            }
        }
        s_r[w] = reg;
    }
    __syncthreads();
    if (threadIdx.x == 0) {
        float cv = 0.0f, rv = 0.0f;
        #pragma unroll
        for (int j = 0; j < 8; j++) { cv += s_c[j]; rv += s_r[j]; }
        g_part[b][blockIdx.x][0] = cv;
        g_part[b][blockIdx.x][1] = rv;
        __threadfence();
        unsigned done = atomicAdd(&g_ticket, 1u);
        s_last = (done == (unsigned)(BB * NPART - 1));
    }
    __syncthreads();
    if (s_last) {
        const float* gp = &g_part[0][0][0];
        int t = threadIdx.x;
        s_fc[t] = gp[2 * t];
        s_fr[t] = gp[2 * t + 1];
        __syncthreads();
        for (int st = 128; st > 0; st >>= 1) {
            if (t < st) { s_fc[t] += s_fc[t + st]; s_fr[t] += s_fr[t + st]; }
            __syncthreads();
        }
        if (t == 0) {
            float cs = s_fc[0] / (float)BB;
            float rs = s_fr[0] / (float)BB;
            out[0] = cs + rs;
            out[1] = cs;
            out[2] = rs;
        }
    }
}

// ---------------- launch ----------------
extern "C" void kernel_launch(void* const* d_in, const int* in_sizes, int n_in,
                              void* d_out, int out_size) {
    const float* box_pred   = (const float*)d_in[0];
    const float* class_pred = (const float*)d_in[1];
    const float* regr_tgt   = (const float*)d_in[2];
    const int*   cls_tgt    = (const int*)d_in[3];
    (void)in_sizes; (void)n_in; (void)out_size;

    cudaFuncSetAttribute(k_select, cudaFuncAttributeMaxDynamicSharedMemorySize,
                         NN * (int)sizeof(u64));

    k_iou<<<dim3(NN / 256, BB), 256>>>(box_pred, regr_tgt);
    k_select<<<2 * BB, SEL_T, NN * sizeof(u64)>>>();
    k_loss<<<dim3(LOSS_BX, BB), 256>>>(box_pred, class_pred, regr_tgt, cls_tgt,
                                       (float*)d_out);
}